// round 15
// baseline (speedup 1.0000x reference)
#include <cuda_runtime.h>
#include <cuda_bf16.h>
#include <math_constants.h>
#include <cstdint>

#define NN 512
#define BB 4
#define HH 4
#define FF 64
#define NCHT 8      // T-partial chunks = 8 m-tiles of 64 rows

// ---------------- scratch (device globals; no allocation) ----------------
__device__ float g_d[NN];
__device__ float g_cpart[32 * NN];
__device__ float g_nor[NN * NN];
__device__ __nv_bfloat16 g_norh[NN * NN];          // nor hi (bf16)
__device__ __nv_bfloat16 g_norl[NN * NN];          // nor lo
__device__ __nv_bfloat16 g_qh[BB * HH * NN * FF];  // q hi (pre-scaled 1/8)
__device__ __nv_bfloat16 g_ql[BB * HH * NN * FF];  // q lo
__device__ __nv_bfloat16 g_kh[BB * HH * NN * FF];  // k hi
__device__ __nv_bfloat16 g_kl[BB * HH * NN * FF];  // k lo
__device__ float g_Tpart[NCHT * BB * HH * NN];

// ---------------- HMMA m16n8k16 bf16 -> f32 ----------------
__device__ __forceinline__ void mma16816(float d[4], const uint32_t a[4],
                                         const uint32_t b[2]) {
    asm volatile(
        "mma.sync.aligned.m16n8k16.row.col.f32.bf16.bf16.f32 "
        "{%0,%1,%2,%3}, {%4,%5,%6,%7}, {%8,%9}, {%0,%1,%2,%3};"
        : "+f"(d[0]), "+f"(d[1]), "+f"(d[2]), "+f"(d[3])
        : "r"(a[0]), "r"(a[1]), "r"(a[2]), "r"(a[3]), "r"(b[0]), "r"(b[1]));
}

__device__ __forceinline__ uint32_t smem_u32(const void* p) {
    uint32_t r;
    asm("{ .reg .u64 t; cvta.to.shared.u64 t, %1; cvt.u32.u64 %0, t; }"
        : "=r"(r) : "l"(p));
    return r;
}
__device__ __forceinline__ void ldsm4(uint32_t r[4], uint32_t addr) {
    asm volatile("ldmatrix.sync.aligned.m8n8.x4.shared.b16 {%0,%1,%2,%3}, [%4];"
                 : "=r"(r[0]), "=r"(r[1]), "=r"(r[2]), "=r"(r[3]) : "r"(addr));
}

// ---------------- cp.async + mbarrier ----------------
#define CP16(dst, src) \
    asm volatile("cp.async.cg.shared.global [%0], [%1], 16;" \
                 :: "r"(dst), "l"(__cvta_generic_to_global(src)) : "memory")
#define CP_ARRIVE(mb) \
    asm volatile("cp.async.mbarrier.arrive.noinc.shared.b64 [%0];" :: "r"(mb) : "memory")
#define CP_COMMIT() asm volatile("cp.async.commit_group;" ::: "memory")
#define CP_WAIT1() asm volatile("cp.async.wait_group 1;" ::: "memory")
#define CP_WAIT0() asm volatile("cp.async.wait_group 0;" ::: "memory")
#define MBAR_INIT(mb, n) \
    asm volatile("mbarrier.init.shared.b64 [%0], %1;" :: "r"(mb), "r"((uint32_t)(n)) : "memory")
#define MBAR_WAIT(mb, ph) do { \
    asm volatile( \
        "{\n\t.reg .pred P1;\n\t" \
        "WAIT_LOOP_%=:\n\t" \
        "mbarrier.try_wait.parity.acquire.cta.shared::cta.b64 P1, [%0], %1, 0x989680;\n\t" \
        "@P1 bra.uni WAIT_DONE_%=;\n\t" \
        "bra.uni WAIT_LOOP_%=;\n\t" \
        "WAIT_DONE_%=:\n\t}" \
        :: "r"(mb), "r"((uint32_t)(ph)) : "memory"); \
} while (0)

__device__ __forceinline__ float blockReduceSum256(float v, float* red) {
    #pragma unroll
    for (int o = 16; o; o >>= 1) v += __shfl_xor_sync(0xffffffffu, v, o);
    int wid = threadIdx.x >> 5, lane = threadIdx.x & 31;
    if (lane == 0) red[wid] = v;
    __syncthreads();
    float r = (threadIdx.x < 8) ? red[threadIdx.x] : 0.f;
    if (wid == 0) {
        #pragma unroll
        for (int o = 4; o; o >>= 1) r += __shfl_xor_sync(0xffffffffu, r, o);
    }
    return r;
}

// ---------------- K1a: degrees ----------------
__global__ void k_deg(const float* __restrict__ adj) {
    __shared__ float red[8];
    int i = blockIdx.x;
    float s = 0.f;
    for (int j = threadIdx.x; j < NN; j += 256) s += adj[i * NN + j];
    s = blockReduceSum256(s, red);
    if (threadIdx.x == 0) g_d[i] = rsqrtf(s + 1.0f);
}

// ---------------- K1b+K2 fused: nor (blocks 0..31) | proj (blocks 32..287)
__global__ __launch_bounds__(512) void k_nor_proj(const float* __restrict__ adj,
                                                  const float* __restrict__ x,
                                                  const float* __restrict__ Wq,
                                                  const float* __restrict__ bq,
                                                  const float* __restrict__ Wk,
                                                  const float* __restrict__ bk) {
    __shared__ float xs[64][65];
    __shared__ float ws[64][64];

    if (blockIdx.x < 32) {
        const int bk_ = blockIdx.x;
        const int j = threadIdx.x;
        const float dj = g_d[j];
        float s = 0.f;
        #pragma unroll
        for (int r = 0; r < 16; r++) {
            int i = bk_ * 16 + r;
            float a = adj[i * NN + j] + (i == j ? 1.0f : 0.0f);
            float v = g_d[i] * dj * a;
            g_nor[i * NN + j] = v;
            __nv_bfloat16 hb = __float2bfloat16(v);
            g_norh[i * NN + j] = hb;
            g_norl[i * NN + j] = __float2bfloat16(v - __bfloat162float(hb));
            s += v;
        }
        g_cpart[bk_ * NN + j] = s;
        return;
    }

    const int pb = blockIdx.x - 32;
    const int px = pb & 31, by = pb >> 5;
    const bool isK = by >= 4;
    const float* W = isK ? Wk : Wq;
    const float* bias = isK ? bk : bq;
    const int h = isK ? by - 4 : by;
    const int c0 = h * 64;
    const int rowBase = px * 64;
    const int b = rowBase >> 9;
    const int bh = b * HH + h;
    const int nb = rowBase & 511;

    const int t = threadIdx.x;
    if (t < 256) {
        #pragma unroll
        for (int i = 0; i < 4; i++) {
            int lin4 = t + i * 256;
            int r = lin4 >> 4, c4 = (lin4 & 15) * 4;
            float4 v = *(const float4*)(x + rowBase * 64 + lin4 * 4);
            xs[r][c4] = v.x; xs[r][c4 + 1] = v.y; xs[r][c4 + 2] = v.z; xs[r][c4 + 3] = v.w;
            *(float4*)&ws[r][c4] = *(const float4*)(W + r * 256 + c0 + c4);
        }
    }
    __syncthreads();
    if (t >= 256) return;

    const int tx = t & 15, ty = t >> 4;
    float acc[4][4];
    #pragma unroll
    for (int i = 0; i < 4; i++)
        #pragma unroll
        for (int jj = 0; jj < 4; jj++) acc[i][jj] = 0.f;

    #pragma unroll 8
    for (int k = 0; k < 64; k++) {
        float a0 = xs[4 * ty + 0][k];
        float a1 = xs[4 * ty + 1][k];
        float a2 = xs[4 * ty + 2][k];
        float a3 = xs[4 * ty + 3][k];
        float4 bv = *(float4*)&ws[k][4 * tx];
        acc[0][0] += a0 * bv.x; acc[0][1] += a0 * bv.y; acc[0][2] += a0 * bv.z; acc[0][3] += a0 * bv.w;
        acc[1][0] += a1 * bv.x; acc[1][1] += a1 * bv.y; acc[1][2] += a1 * bv.z; acc[1][3] += a1 * bv.w;
        acc[2][0] += a2 * bv.x; acc[2][1] += a2 * bv.y; acc[2][2] += a2 * bv.z; acc[2][3] += a2 * bv.w;
        acc[3][0] += a3 * bv.x; acc[3][1] += a3 * bv.y; acc[3][2] += a3 * bv.z; acc[3][3] += a3 * bv.w;
    }

    float4 bb = *(const float4*)&bias[c0 + 4 * tx];
    const float sc = isK ? 1.0f : 0.125f;
    __nv_bfloat16* dh = isK ? g_kh : g_qh;
    __nv_bfloat16* dl = isK ? g_kl : g_ql;
    #pragma unroll
    for (int rr = 0; rr < 4; rr++) {
        int n = nb + 4 * ty + rr;
        size_t o = (size_t)(bh * NN + n) * FF + 4 * tx;
        float v0 = (acc[rr][0] + bb.x) * sc;
        float v1 = (acc[rr][1] + bb.y) * sc;
        float v2 = (acc[rr][2] + bb.z) * sc;
        float v3 = (acc[rr][3] + bb.w) * sc;
        __nv_bfloat16 h0 = __float2bfloat16(v0), h1 = __float2bfloat16(v1);
        __nv_bfloat16 h2 = __float2bfloat16(v2), h3 = __float2bfloat16(v3);
        *(__nv_bfloat162*)&dh[o]     = __halves2bfloat162(h0, h1);
        *(__nv_bfloat162*)&dh[o + 2] = __halves2bfloat162(h2, h3);
        *(__nv_bfloat162*)&dl[o] = __halves2bfloat162(
            __float2bfloat16(v0 - __bfloat162float(h0)),
            __float2bfloat16(v1 - __bfloat162float(h1)));
        *(__nv_bfloat162*)&dl[o + 2] = __halves2bfloat162(
            __float2bfloat16(v2 - __bfloat162float(h2)),
            __float2bfloat16(v3 - __bfloat162float(h3)));
    }
}

// ---------------- K3: HMMA scores, cp.async-pipelined (unchanged) -------
#define ATTN_DSM 223232
__global__ __launch_bounds__(512, 1) void k_attn_mma() {
    extern __shared__ __align__(16) char dsm[];
    __nv_bfloat16* qh_s = (__nv_bfloat16*)dsm;
    __nv_bfloat16* kh_s = (__nv_bfloat16*)(dsm + 9216);
    __nv_bfloat16* kl_s = (__nv_bfloat16*)(dsm + 82944);
    __nv_bfloat16* expb = (__nv_bfloat16*)(dsm + 156672);

    __shared__ unsigned long long mbars[4];
    __shared__ float rsum[4][64];
    __shared__ float rinv[64];

    const int mtile = blockIdx.x, h = blockIdx.y, b = blockIdx.z;
    const int bh = b * HH + h;
    const int iBase = mtile * 64;
    const int tid = threadIdx.x;
    const int w = tid >> 5, lane = tid & 31;
    const int mrow = (w >> 2) * 16;
    const int cs = w & 3;
    const int r = lane >> 2, c = lane & 3;

    const uint32_t qh_b = smem_u32(qh_s);
    const uint32_t kh_b = smem_u32(kh_s);
    const uint32_t kl_b = smem_u32(kl_s);

    if (tid < 4) MBAR_INIT(smem_u32(&mbars[tid]), 512);

    {
        const uint4* sh = (const uint4*)(g_qh + (size_t)(bh * NN + iBase) * FF);
        int row = tid >> 3, c8 = tid & 7;
        *(uint4*)&qh_s[row * 72 + c8 * 8] = sh[tid];
    }
    __syncthreads();

    {
        const char* khg = (const char*)(g_kh + (size_t)bh * NN * FF);
        const char* klg = (const char*)(g_kl + (size_t)bh * NN * FF);
        #pragma unroll
        for (int ch = 0; ch < 4; ch++) {
            #pragma unroll
            for (int i = 0; i < 2; i++) {
                int idx = tid + i * 512;
                int row = ch * 128 + (idx >> 3), c8 = idx & 7;
                CP16(kh_b + (uint32_t)(row * 144 + c8 * 16), khg + row * 128 + c8 * 16);
                CP16(kl_b + (uint32_t)(row * 144 + c8 * 16), klg + row * 128 + c8 * 16);
            }
            CP_ARRIVE(smem_u32(&mbars[ch]));
        }
    }

    uint32_t qhA[4][4], qlA[4][4];
    {
        const int arow = mrow + (lane & 7) + ((lane >> 3) & 1) * 8;
        const uint32_t aoff = (uint32_t)(arow * 72 + (lane >> 4) * 8) * 2;
        #pragma unroll
        for (int kt = 0; kt < 4; kt++) ldsm4(qhA[kt], qh_b + aoff + kt * 32);
        const __nv_bfloat16* qlg = g_ql + (size_t)(bh * NN + iBase) * FF;
        #pragma unroll
        for (int kt = 0; kt < 4; kt++) {
            int col = kt * 16 + 2 * c;
            qlA[kt][0] = *(const uint32_t*)&qlg[(mrow + r) * 64 + col];
            qlA[kt][1] = *(const uint32_t*)&qlg[(mrow + r + 8) * 64 + col];
            qlA[kt][2] = *(const uint32_t*)&qlg[(mrow + r) * 64 + col + 8];
            qlA[kt][3] = *(const uint32_t*)&qlg[(mrow + r + 8) * 64 + col + 8];
        }
    }

    MBAR_WAIT(smem_u32(&mbars[cs]), 0);

    float rs0 = 0.f, rs1 = 0.f;
    const int brow0 = cs * 128 + (lane & 7);
    const uint32_t boff_lane = (uint32_t)((lane >> 3) * 16);

    #pragma unroll 2
    for (int nt = 0; nt < 16; nt++) {
        const uint32_t bb = (uint32_t)((brow0 + nt * 8) * 144) + boff_lane;
        uint32_t khx[8], klx[8];
        ldsm4(khx, kh_b + bb);
        ldsm4(khx + 4, kh_b + bb + 64);
        ldsm4(klx, kl_b + bb);
        ldsm4(klx + 4, kl_b + bb + 64);

        float d0[4] = {0.f, 0.f, 0.f, 0.f};
        float d1[4] = {0.f, 0.f, 0.f, 0.f};
        float d2[4] = {0.f, 0.f, 0.f, 0.f};
        #pragma unroll
        for (int kt = 0; kt < 4; kt++) {
            mma16816(d0, qhA[kt], khx + 2 * kt);
            mma16816(d1, qhA[kt], klx + 2 * kt);
            mma16816(d2, qlA[kt], khx + 2 * kt);
        }
        float e0 = __expf(d0[0] + d1[0] + d2[0]);
        float e1 = __expf(d0[1] + d1[1] + d2[1]);
        float e2 = __expf(d0[2] + d1[2] + d2[2]);
        float e3 = __expf(d0[3] + d1[3] + d2[3]);
        rs0 += e0 + e1;
        rs1 += e2 + e3;
        int gcol = cs * 128 + nt * 8 + 2 * c;
        *(__nv_bfloat162*)&expb[(mrow + r) * 520 + gcol] =
            __halves2bfloat162(__float2bfloat16(e0), __float2bfloat16(e1));
        *(__nv_bfloat162*)&expb[(mrow + r + 8) * 520 + gcol] =
            __halves2bfloat162(__float2bfloat16(e2), __float2bfloat16(e3));
    }

    rs0 += __shfl_xor_sync(0xffffffffu, rs0, 1);
    rs0 += __shfl_xor_sync(0xffffffffu, rs0, 2);
    rs1 += __shfl_xor_sync(0xffffffffu, rs1, 1);
    rs1 += __shfl_xor_sync(0xffffffffu, rs1, 2);
    if ((lane & 3) == 0) {
        rsum[cs][mrow + r] = rs0;
        rsum[cs][mrow + r + 8] = rs1;
    }
    __syncthreads();
    if (tid < 64)
        rinv[tid] = 1.0f / (rsum[0][tid] + rsum[1][tid] + rsum[2][tid] + rsum[3][tid]);
    __syncthreads();

    {
        const float* np = g_nor + (size_t)iBase * NN;
        float a0 = 0.f, a1 = 0.f;
        #pragma unroll 8
        for (int i = 0; i < 64; i += 2) {
            a0 += np[i * NN + tid] *
                  (__bfloat162float(expb[i * 520 + tid]) * rinv[i]);
            a1 += np[(i + 1) * NN + tid] *
                  (__bfloat162float(expb[(i + 1) * 520 + tid]) * rinv[i + 1]);
        }
        g_Tpart[mtile * (BB * HH * NN) + bh * NN + tid] = a0 + a1;
    }
}

// ---------------- K4: fused sx + HMMA out = relu((nor@sx)@Wfc + bfc) ----
// grid (8 mtiles, B) = 32 blocks, 512 threads (16 warps: 4 m x 4 n).
// sx^T [64 f][520 j] bf16 hi/lo RESIDENT in smem; nor hi/lo streamed in a
// 2-stage cp.async pipeline (FULL 256B per row: 2 CP16 per thread per array).
#define SXH_OFF 0
#define SXL_OFF 66560
#define STG_OFF 133120
#define WFC_OFF 202752
#define TS_OFF  219136
#define CS_OFF  227328
#define OUT_DSM 229376

__device__ __forceinline__ void nor_fill(uint32_t stg, int iBase, int kc, int t) {
    const char* sh = (const char*)(g_norh + (size_t)iBase * NN) + kc * 256;
    const char* sl = (const char*)(g_norl + (size_t)iBase * NN) + kc * 256;
    #pragma unroll
    for (int i = 0; i < 2; i++) {
        int idx = t + i * 512;            // 0..1023
        int row = idx >> 4, seg = idx & 15;   // 64 rows x 16 segs x 16B = 256B/row
        CP16(stg + row * 272 + seg * 16, sh + (size_t)row * 1024 + seg * 16);
        CP16(stg + 17408 + row * 272 + seg * 16, sl + (size_t)row * 1024 + seg * 16);
    }
}

__global__ __launch_bounds__(512, 1) void k_out_mma(const float* __restrict__ x,
                                                    const float* __restrict__ Wlin,
                                                    const float* __restrict__ blin,
                                                    const float* __restrict__ Wfc,
                                                    const float* __restrict__ bfc,
                                                    float* __restrict__ out) {
    extern __shared__ __align__(16) char dsm[];
    __nv_bfloat16* sxh = (__nv_bfloat16*)(dsm + SXH_OFF);
    __nv_bfloat16* sxl = (__nv_bfloat16*)(dsm + SXL_OFF);
    float* wfcs = (float*)(dsm + WFC_OFF);
    float* Ts = (float*)(dsm + TS_OFF);   // [4][512]
    float* cs = (float*)(dsm + CS_OFF);   // [512]
    float* tmp = (float*)(dsm + STG_OFF); // overlay after MMAs, [64][68]

    const int mtile = blockIdx.x;
    const int b = blockIdx.y;
    const int iBase = mtile * 64;
    const int t = threadIdx.x, w = t >> 5, lane = t & 31;
    const int ms = w >> 2, ns = w & 3;
    const uint32_t dsm_b = smem_u32(dsm);
    const uint32_t stg_b = dsm_b + STG_OFF;
    const uint32_t sxh_b = dsm_b + SXH_OFF;
    const uint32_t sxl_b = dsm_b + SXL_OFF;

    // 1. kick off nor stage fills (overlap with sx phase)
    nor_fill(stg_b, iBase, 0, t);
    CP_COMMIT();
    nor_fill(stg_b + 34816, iBase, 1, t);
    CP_COMMIT();

    // 2. Wfc -> smem (plain loads)
    #pragma unroll
    for (int i = 0; i < 2; i++)
        ((float4*)wfcs)[t + i * 512] = ((const float4*)Wfc)[t + i * 512];

    // 3. T and c reductions (per-thread column t, coalesced)
    {
        #pragma unroll
        for (int h = 0; h < HH; h++) {
            float s = 0.f;
            #pragma unroll
            for (int ch = 0; ch < NCHT; ch++)
                s += g_Tpart[ch * (BB * HH * NN) + (b * HH + h) * NN + t];
            Ts[h * NN + t] = s;
        }
        float s = 0.f;
        #pragma unroll
        for (int p = 0; p < 32; p++) s += g_cpart[p * NN + t];
        cs[t] = s;
    }
    __syncthreads();

    // 4. compute sx^T hi/lo into resident smem.
    {
        const int g = t >> 6, j0 = t & 63;
        const int f0 = g * 8;
        float bl[8], wl[HH][8];
        #pragma unroll
        for (int i = 0; i < 8; i++) bl[i] = blin[f0 + i];
        #pragma unroll
        for (int h = 0; h < HH; h++)
            #pragma unroll
            for (int i = 0; i < 8; i++) wl[h][i] = Wlin[h * FF + f0 + i];

        for (int p = 0; p < 8; p++) {
            int j = p * 64 + j0;
            const float* xp = x + ((size_t)(b * NN) + j) * FF + f0;
            float4 xa = *(const float4*)xp;
            float4 xb = *(const float4*)(xp + 4);
            float xv[8] = {xa.x, xa.y, xa.z, xa.w, xb.x, xb.y, xb.z, xb.w};
            float cj = cs[j];
            float th[HH];
            #pragma unroll
            for (int h = 0; h < HH; h++) th[h] = Ts[h * NN + j];
            #pragma unroll
            for (int i = 0; i < 8; i++) {
                float s = cj * bl[i];
                #pragma unroll
                for (int h = 0; h < HH; h++) s += th[h] * wl[h][i];
                float v = xv[i] * s;
                __nv_bfloat16 hb = __float2bfloat16(v);
                sxh[(f0 + i) * 520 + j] = hb;
                sxl[(f0 + i) * 520 + j] =
                    __float2bfloat16(v - __bfloat162float(hb));
            }
        }
    }
    __syncthreads();

    // 5. MMA mainloop: A = nor (staged), B = sx^T (resident)
    float acc0[4] = {0.f, 0.f, 0.f, 0.f};
    float acc1[4] = {0.f, 0.f, 0.f, 0.f};

    const int arow = ms * 16 + (lane & 7) + ((lane >> 3) & 1) * 8;
    const uint32_t aoff = (uint32_t)(arow * 272 + (lane >> 4) * 16);
    const uint32_t bbase = (uint32_t)((ns * 16 + (lane & 7)) * 1040 + (lane >> 3) * 16);
    const uint32_t bbase1 = bbase + 8 * 1040;

    #pragma unroll
    for (int kc = 0; kc < 4; kc++) {
        if (kc < 3) CP_WAIT1(); else CP_WAIT0();
        __syncthreads();

        const uint32_t nh = stg_b + (kc & 1) * 34816;
        const uint32_t nl = nh + 17408;
        const uint32_t bcol = (uint32_t)kc * 256;

        #pragma unroll
        for (int kg = 0; kg < 4; kg++) {
            uint32_t Ah0[4], Ah1[4], Al0[4], Al1[4];
            ldsm4(Ah0, nh + aoff + (kg * 2) * 32);
            ldsm4(Ah1, nh + aoff + (kg * 2 + 1) * 32);
            ldsm4(Al0, nl + aoff + (kg * 2) * 32);
            ldsm4(Al1, nl + aoff + (kg * 2 + 1) * 32);
            uint32_t Bh0[4], Bh1[4], Bl0[4], Bl1[4];
            ldsm4(Bh0, sxh_b + bbase + bcol + kg * 64);
            ldsm4(Bh1, sxh_b + bbase1 + bcol + kg * 64);
            ldsm4(Bl0, sxl_b + bbase + bcol + kg * 64);
            ldsm4(Bl1, sxl_b + bbase1 + bcol + kg * 64);

            mma16816(acc0, Ah0, Bh0);     mma16816(acc0, Ah1, Bh0 + 2);
            mma16816(acc1, Ah0, Bh1);     mma16816(acc1, Ah1, Bh1 + 2);
            mma16816(acc0, Ah0, Bl0);     mma16816(acc0, Ah1, Bl0 + 2);
            mma16816(acc1, Ah0, Bl1);     mma16816(acc1, Ah1, Bl1 + 2);
            mma16816(acc0, Al0, Bh0);     mma16816(acc0, Al1, Bh0 + 2);
            mma16816(acc1, Al0, Bh1);     mma16816(acc1, Al1, Bh1 + 2);
        }
        __syncthreads();
        if (kc < 2) {
            nor_fill(stg_b + (kc & 1) * 34816, iBase, kc + 2, t);
            CP_COMMIT();
        }
    }

    // 6. accumulators -> tmp (stage overlay), fc epilogue, relu, store
    {
        int r = lane >> 2, c2 = (lane & 3) * 2;
        int col0 = ns * 16 + c2;
        tmp[(ms * 16 + r) * 68 + col0]         = acc0[0];
        tmp[(ms * 16 + r) * 68 + col0 + 1]     = acc0[1];
        tmp[(ms * 16 + r + 8) * 68 + col0]     = acc0[2];
        tmp[(ms * 16 + r + 8) * 68 + col0 + 1] = acc0[3];
        tmp[(ms * 16 + r) * 68 + col0 + 8]         = acc1[0];
        tmp[(ms * 16 + r) * 68 + col0 + 9]         = acc1[1];
        tmp[(ms * 16 + r + 8) * 68 + col0 + 8]     = acc1[2];
        tmp[(ms * 16 + r + 8) * 68 + col0 + 9]     = acc1[3];
    }
    __syncthreads();

    {
        int row = t >> 3, fo = (t & 7) * 8;
        float o[8];
        #pragma unroll
        for (int i = 0; i < 8; i++) o[i] = bfc[fo + i];
        #pragma unroll 8
        for (int ff = 0; ff < 64; ff++) {
            float a = tmp[row * 68 + ff];
            const float* wr = wfcs + ff * 64 + fo;
            #pragma unroll
            for (int i = 0; i < 8; i++) o[i] += a * wr[i];
        }
        float* op = out + ((size_t)(b * NN) + iBase + row) * FF + fo;
        #pragma unroll
        for (int i = 0; i < 8; i++) op[i] = fmaxf(o[i], 0.f);
    }
}

// ---------------- launch ----------------
extern "C" void kernel_launch(void* const* d_in, const int* in_sizes, int n_in,
                              void* d_out, int out_size) {
    const float* x    = (const float*)d_in[0];
    const float* adj  = (const float*)d_in[1];
    const float* Wq   = (const float*)d_in[2];
    const float* bq   = (const float*)d_in[3];
    const float* Wk   = (const float*)d_in[4];
    const float* bk   = (const float*)d_in[5];
    const float* Wlin = (const float*)d_in[6];
    const float* blin = (const float*)d_in[7];
    const float* Wfc  = (const float*)d_in[8];
    const float* bfc  = (const float*)d_in[9];
    float* out = (float*)d_out;

    static int attr_set = 0;
    if (!attr_set) {
        cudaFuncSetAttribute(k_attn_mma,
                             cudaFuncAttributeMaxDynamicSharedMemorySize, ATTN_DSM);
        cudaFuncSetAttribute(k_out_mma,
                             cudaFuncAttributeMaxDynamicSharedMemorySize, OUT_DSM);
        attr_set = 1;
    }

    k_deg<<<NN, 256>>>(adj);
    k_nor_proj<<<288, 512>>>(adj, x, Wq, bq, Wk, bk);
    k_attn_mma<<<dim3(8, HH, BB), 512, ATTN_DSM>>>();
    k_out_mma<<<dim3(8, BB), 512, OUT_DSM>>>(x, Wlin, blin, Wfc, bfc, out);
}

// round 16
// speedup vs baseline: 1.1412x; 1.1412x over previous
#include <cuda_runtime.h>
#include <cuda_bf16.h>
#include <math_constants.h>
#include <cstdint>

#define NN 512
#define BB 4
#define HH 4
#define FF 64
#define NCHT 8      // T-partial chunks = 8 m-tiles of 64 rows

// ---------------- scratch (device globals; no allocation) ----------------
__device__ float g_d[NN];
__device__ float g_cpart[32 * NN];
__device__ float g_nor[NN * NN];
__device__ __nv_bfloat16 g_norh[NN * NN];          // nor hi (bf16)
__device__ __nv_bfloat16 g_norl[NN * NN];          // nor lo
__device__ __nv_bfloat16 g_qh[BB * HH * NN * FF];  // q hi (pre-scaled 1/8)
__device__ __nv_bfloat16 g_ql[BB * HH * NN * FF];  // q lo
__device__ __nv_bfloat16 g_kh[BB * HH * NN * FF];  // k hi
__device__ __nv_bfloat16 g_kl[BB * HH * NN * FF];  // k lo
__device__ float g_Tpart[NCHT * BB * HH * NN];
__device__ float g_opart[4 * BB * NN * FF];        // [ks][b][512][64] fp32

// ---------------- HMMA m16n8k16 bf16 -> f32 ----------------
__device__ __forceinline__ void mma16816(float d[4], const uint32_t a[4],
                                         const uint32_t b[2]) {
    asm volatile(
        "mma.sync.aligned.m16n8k16.row.col.f32.bf16.bf16.f32 "
        "{%0,%1,%2,%3}, {%4,%5,%6,%7}, {%8,%9}, {%0,%1,%2,%3};"
        : "+f"(d[0]), "+f"(d[1]), "+f"(d[2]), "+f"(d[3])
        : "r"(a[0]), "r"(a[1]), "r"(a[2]), "r"(a[3]), "r"(b[0]), "r"(b[1]));
}

__device__ __forceinline__ uint32_t smem_u32(const void* p) {
    uint32_t r;
    asm("{ .reg .u64 t; cvta.to.shared.u64 t, %1; cvt.u32.u64 %0, t; }"
        : "=r"(r) : "l"(p));
    return r;
}
__device__ __forceinline__ void ldsm4(uint32_t r[4], uint32_t addr) {
    asm volatile("ldmatrix.sync.aligned.m8n8.x4.shared.b16 {%0,%1,%2,%3}, [%4];"
                 : "=r"(r[0]), "=r"(r[1]), "=r"(r[2]), "=r"(r[3]) : "r"(addr));
}

// ---------------- cp.async + mbarrier ----------------
#define CP16(dst, src) \
    asm volatile("cp.async.cg.shared.global [%0], [%1], 16;" \
                 :: "r"(dst), "l"(__cvta_generic_to_global(src)) : "memory")
#define CP_ARRIVE(mb) \
    asm volatile("cp.async.mbarrier.arrive.noinc.shared.b64 [%0];" :: "r"(mb) : "memory")
#define CP_COMMIT() asm volatile("cp.async.commit_group;" ::: "memory")
#define CP_WAIT0() asm volatile("cp.async.wait_group 0;" ::: "memory")
#define MBAR_INIT(mb, n) \
    asm volatile("mbarrier.init.shared.b64 [%0], %1;" :: "r"(mb), "r"((uint32_t)(n)) : "memory")
#define MBAR_WAIT(mb, ph) do { \
    asm volatile( \
        "{\n\t.reg .pred P1;\n\t" \
        "WAIT_LOOP_%=:\n\t" \
        "mbarrier.try_wait.parity.acquire.cta.shared::cta.b64 P1, [%0], %1, 0x989680;\n\t" \
        "@P1 bra.uni WAIT_DONE_%=;\n\t" \
        "bra.uni WAIT_LOOP_%=;\n\t" \
        "WAIT_DONE_%=:\n\t}" \
        :: "r"(mb), "r"((uint32_t)(ph)) : "memory"); \
} while (0)

__device__ __forceinline__ float blockReduceSum256(float v, float* red) {
    #pragma unroll
    for (int o = 16; o; o >>= 1) v += __shfl_xor_sync(0xffffffffu, v, o);
    int wid = threadIdx.x >> 5, lane = threadIdx.x & 31;
    if (lane == 0) red[wid] = v;
    __syncthreads();
    float r = (threadIdx.x < 8) ? red[threadIdx.x] : 0.f;
    if (wid == 0) {
        #pragma unroll
        for (int o = 4; o; o >>= 1) r += __shfl_xor_sync(0xffffffffu, r, o);
    }
    return r;
}

// ---------------- K1a: degrees ----------------
__global__ void k_deg(const float* __restrict__ adj) {
    __shared__ float red[8];
    int i = blockIdx.x;
    float s = 0.f;
    for (int j = threadIdx.x; j < NN; j += 256) s += adj[i * NN + j];
    s = blockReduceSum256(s, red);
    if (threadIdx.x == 0) g_d[i] = rsqrtf(s + 1.0f);
}

// ---------------- K1b+K2 fused: nor (blocks 0..31) | proj (blocks 32..287)
__global__ __launch_bounds__(512) void k_nor_proj(const float* __restrict__ adj,
                                                  const float* __restrict__ x,
                                                  const float* __restrict__ Wq,
                                                  const float* __restrict__ bq,
                                                  const float* __restrict__ Wk,
                                                  const float* __restrict__ bk) {
    __shared__ float xs[64][65];
    __shared__ float ws[64][64];

    if (blockIdx.x < 32) {
        const int bk_ = blockIdx.x;
        const int j = threadIdx.x;
        const float dj = g_d[j];
        float s = 0.f;
        #pragma unroll
        for (int r = 0; r < 16; r++) {
            int i = bk_ * 16 + r;
            float a = adj[i * NN + j] + (i == j ? 1.0f : 0.0f);
            float v = g_d[i] * dj * a;
            g_nor[i * NN + j] = v;
            __nv_bfloat16 hb = __float2bfloat16(v);
            g_norh[i * NN + j] = hb;
            g_norl[i * NN + j] = __float2bfloat16(v - __bfloat162float(hb));
            s += v;
        }
        g_cpart[bk_ * NN + j] = s;
        return;
    }

    const int pb = blockIdx.x - 32;
    const int px = pb & 31, by = pb >> 5;
    const bool isK = by >= 4;
    const float* W = isK ? Wk : Wq;
    const float* bias = isK ? bk : bq;
    const int h = isK ? by - 4 : by;
    const int c0 = h * 64;
    const int rowBase = px * 64;
    const int b = rowBase >> 9;
    const int bh = b * HH + h;
    const int nb = rowBase & 511;

    const int t = threadIdx.x;
    if (t < 256) {
        #pragma unroll
        for (int i = 0; i < 4; i++) {
            int lin4 = t + i * 256;
            int r = lin4 >> 4, c4 = (lin4 & 15) * 4;
            float4 v = *(const float4*)(x + rowBase * 64 + lin4 * 4);
            xs[r][c4] = v.x; xs[r][c4 + 1] = v.y; xs[r][c4 + 2] = v.z; xs[r][c4 + 3] = v.w;
            *(float4*)&ws[r][c4] = *(const float4*)(W + r * 256 + c0 + c4);
        }
    }
    __syncthreads();
    if (t >= 256) return;

    const int tx = t & 15, ty = t >> 4;
    float acc[4][4];
    #pragma unroll
    for (int i = 0; i < 4; i++)
        #pragma unroll
        for (int jj = 0; jj < 4; jj++) acc[i][jj] = 0.f;

    #pragma unroll 8
    for (int k = 0; k < 64; k++) {
        float a0 = xs[4 * ty + 0][k];
        float a1 = xs[4 * ty + 1][k];
        float a2 = xs[4 * ty + 2][k];
        float a3 = xs[4 * ty + 3][k];
        float4 bv = *(float4*)&ws[k][4 * tx];
        acc[0][0] += a0 * bv.x; acc[0][1] += a0 * bv.y; acc[0][2] += a0 * bv.z; acc[0][3] += a0 * bv.w;
        acc[1][0] += a1 * bv.x; acc[1][1] += a1 * bv.y; acc[1][2] += a1 * bv.z; acc[1][3] += a1 * bv.w;
        acc[2][0] += a2 * bv.x; acc[2][1] += a2 * bv.y; acc[2][2] += a2 * bv.z; acc[2][3] += a2 * bv.w;
        acc[3][0] += a3 * bv.x; acc[3][1] += a3 * bv.y; acc[3][2] += a3 * bv.z; acc[3][3] += a3 * bv.w;
    }

    float4 bb = *(const float4*)&bias[c0 + 4 * tx];
    const float sc = isK ? 1.0f : 0.125f;
    __nv_bfloat16* dh = isK ? g_kh : g_qh;
    __nv_bfloat16* dl = isK ? g_kl : g_ql;
    #pragma unroll
    for (int rr = 0; rr < 4; rr++) {
        int n = nb + 4 * ty + rr;
        size_t o = (size_t)(bh * NN + n) * FF + 4 * tx;
        float v0 = (acc[rr][0] + bb.x) * sc;
        float v1 = (acc[rr][1] + bb.y) * sc;
        float v2 = (acc[rr][2] + bb.z) * sc;
        float v3 = (acc[rr][3] + bb.w) * sc;
        __nv_bfloat16 h0 = __float2bfloat16(v0), h1 = __float2bfloat16(v1);
        __nv_bfloat16 h2 = __float2bfloat16(v2), h3 = __float2bfloat16(v3);
        *(__nv_bfloat162*)&dh[o]     = __halves2bfloat162(h0, h1);
        *(__nv_bfloat162*)&dh[o + 2] = __halves2bfloat162(h2, h3);
        *(__nv_bfloat162*)&dl[o] = __halves2bfloat162(
            __float2bfloat16(v0 - __bfloat162float(h0)),
            __float2bfloat16(v1 - __bfloat162float(h1)));
        *(__nv_bfloat162*)&dl[o + 2] = __halves2bfloat162(
            __float2bfloat16(v2 - __bfloat162float(h2)),
            __float2bfloat16(v3 - __bfloat162float(h3)));
    }
}

// ---------------- K3: HMMA scores, cp.async-pipelined (unchanged) -------
#define ATTN_DSM 223232
__global__ __launch_bounds__(512, 1) void k_attn_mma() {
    extern __shared__ __align__(16) char dsm[];
    __nv_bfloat16* qh_s = (__nv_bfloat16*)dsm;
    __nv_bfloat16* kh_s = (__nv_bfloat16*)(dsm + 9216);
    __nv_bfloat16* kl_s = (__nv_bfloat16*)(dsm + 82944);
    __nv_bfloat16* expb = (__nv_bfloat16*)(dsm + 156672);

    __shared__ unsigned long long mbars[4];
    __shared__ float rsum[4][64];
    __shared__ float rinv[64];

    const int mtile = blockIdx.x, h = blockIdx.y, b = blockIdx.z;
    const int bh = b * HH + h;
    const int iBase = mtile * 64;
    const int tid = threadIdx.x;
    const int w = tid >> 5, lane = tid & 31;
    const int mrow = (w >> 2) * 16;
    const int cs = w & 3;
    const int r = lane >> 2, c = lane & 3;

    const uint32_t qh_b = smem_u32(qh_s);
    const uint32_t kh_b = smem_u32(kh_s);
    const uint32_t kl_b = smem_u32(kl_s);

    if (tid < 4) MBAR_INIT(smem_u32(&mbars[tid]), 512);

    {
        const uint4* sh = (const uint4*)(g_qh + (size_t)(bh * NN + iBase) * FF);
        int row = tid >> 3, c8 = tid & 7;
        *(uint4*)&qh_s[row * 72 + c8 * 8] = sh[tid];
    }
    __syncthreads();

    {
        const char* khg = (const char*)(g_kh + (size_t)bh * NN * FF);
        const char* klg = (const char*)(g_kl + (size_t)bh * NN * FF);
        #pragma unroll
        for (int ch = 0; ch < 4; ch++) {
            #pragma unroll
            for (int i = 0; i < 2; i++) {
                int idx = tid + i * 512;
                int row = ch * 128 + (idx >> 3), c8 = idx & 7;
                CP16(kh_b + (uint32_t)(row * 144 + c8 * 16), khg + row * 128 + c8 * 16);
                CP16(kl_b + (uint32_t)(row * 144 + c8 * 16), klg + row * 128 + c8 * 16);
            }
            CP_ARRIVE(smem_u32(&mbars[ch]));
        }
    }

    uint32_t qhA[4][4], qlA[4][4];
    {
        const int arow = mrow + (lane & 7) + ((lane >> 3) & 1) * 8;
        const uint32_t aoff = (uint32_t)(arow * 72 + (lane >> 4) * 8) * 2;
        #pragma unroll
        for (int kt = 0; kt < 4; kt++) ldsm4(qhA[kt], qh_b + aoff + kt * 32);
        const __nv_bfloat16* qlg = g_ql + (size_t)(bh * NN + iBase) * FF;
        #pragma unroll
        for (int kt = 0; kt < 4; kt++) {
            int col = kt * 16 + 2 * c;
            qlA[kt][0] = *(const uint32_t*)&qlg[(mrow + r) * 64 + col];
            qlA[kt][1] = *(const uint32_t*)&qlg[(mrow + r + 8) * 64 + col];
            qlA[kt][2] = *(const uint32_t*)&qlg[(mrow + r) * 64 + col + 8];
            qlA[kt][3] = *(const uint32_t*)&qlg[(mrow + r + 8) * 64 + col + 8];
        }
    }

    MBAR_WAIT(smem_u32(&mbars[cs]), 0);

    float rs0 = 0.f, rs1 = 0.f;
    const int brow0 = cs * 128 + (lane & 7);
    const uint32_t boff_lane = (uint32_t)((lane >> 3) * 16);

    #pragma unroll 2
    for (int nt = 0; nt < 16; nt++) {
        const uint32_t bb = (uint32_t)((brow0 + nt * 8) * 144) + boff_lane;
        uint32_t khx[8], klx[8];
        ldsm4(khx, kh_b + bb);
        ldsm4(khx + 4, kh_b + bb + 64);
        ldsm4(klx, kl_b + bb);
        ldsm4(klx + 4, kl_b + bb + 64);

        float d0[4] = {0.f, 0.f, 0.f, 0.f};
        float d1[4] = {0.f, 0.f, 0.f, 0.f};
        float d2[4] = {0.f, 0.f, 0.f, 0.f};
        #pragma unroll
        for (int kt = 0; kt < 4; kt++) {
            mma16816(d0, qhA[kt], khx + 2 * kt);
            mma16816(d1, qhA[kt], klx + 2 * kt);
            mma16816(d2, qlA[kt], khx + 2 * kt);
        }
        float e0 = __expf(d0[0] + d1[0] + d2[0]);
        float e1 = __expf(d0[1] + d1[1] + d2[1]);
        float e2 = __expf(d0[2] + d1[2] + d2[2]);
        float e3 = __expf(d0[3] + d1[3] + d2[3]);
        rs0 += e0 + e1;
        rs1 += e2 + e3;
        int gcol = cs * 128 + nt * 8 + 2 * c;
        *(__nv_bfloat162*)&expb[(mrow + r) * 520 + gcol] =
            __halves2bfloat162(__float2bfloat16(e0), __float2bfloat16(e1));
        *(__nv_bfloat162*)&expb[(mrow + r + 8) * 520 + gcol] =
            __halves2bfloat162(__float2bfloat16(e2), __float2bfloat16(e3));
    }

    rs0 += __shfl_xor_sync(0xffffffffu, rs0, 1);
    rs0 += __shfl_xor_sync(0xffffffffu, rs0, 2);
    rs1 += __shfl_xor_sync(0xffffffffu, rs1, 1);
    rs1 += __shfl_xor_sync(0xffffffffu, rs1, 2);
    if ((lane & 3) == 0) {
        rsum[cs][mrow + r] = rs0;
        rsum[cs][mrow + r + 8] = rs1;
    }
    __syncthreads();
    if (tid < 64)
        rinv[tid] = 1.0f / (rsum[0][tid] + rsum[1][tid] + rsum[2][tid] + rsum[3][tid]);
    __syncthreads();

    {
        const float* np = g_nor + (size_t)iBase * NN;
        float a0 = 0.f, a1 = 0.f;
        #pragma unroll 8
        for (int i = 0; i < 64; i += 2) {
            a0 += np[i * NN + tid] *
                  (__bfloat162float(expb[i * 520 + tid]) * rinv[i]);
            a1 += np[(i + 1) * NN + tid] *
                  (__bfloat162float(expb[(i + 1) * 520 + tid]) * rinv[i + 1]);
        }
        g_Tpart[mtile * (BB * HH * NN) + bh * NN + tid] = a0 + a1;
    }
}

// ---------------- K4a: k-split partial out = nor[64x128] @ sx[128x64] ----
// grid (8 mtile, 4 b, 4 ksplit) = 128 blocks, 512 threads (16 warps 4m x 4n).
// Per block: T/c reduce for 128 j, sx hi/lo into smem, nor hi/lo one cp.async
// fill, K=128 MMA, partial fp32 -> g_opart.
#define OP_SXH  0
#define OP_SXL  17408
#define OP_NORH 34816
#define OP_NORL 52224
#define OP_TS   69632
#define OP_CS   71680
#define OP_REDC 72192
#define OP_WLIN 74240
#define OP_BLIN 75264
#define OP_DSM  75520
__global__ __launch_bounds__(512, 1) void k_out_part(const float* __restrict__ x,
                                                     const float* __restrict__ Wlin,
                                                     const float* __restrict__ blin) {
    extern __shared__ __align__(16) char dsm[];
    __nv_bfloat16* sxh = (__nv_bfloat16*)(dsm + OP_SXH);   // [64 f][136 j]
    __nv_bfloat16* sxl = (__nv_bfloat16*)(dsm + OP_SXL);
    float* Ts = (float*)(dsm + OP_TS);       // [4][128]
    float* cs = (float*)(dsm + OP_CS);       // [128]
    float* redC = (float*)(dsm + OP_REDC);   // [4][128]
    float* wlin = (float*)(dsm + OP_WLIN);
    float* blin_s = (float*)(dsm + OP_BLIN);

    const int mtile = blockIdx.x, b = blockIdx.y, ks = blockIdx.z;
    const int iBase = mtile * 64;
    const int jBase = ks * 128;
    const int t = threadIdx.x, w = t >> 5, lane = t & 31;
    const int ms = w >> 2, ns = w & 3;
    const uint32_t dsm_b = smem_u32(dsm);

    // nor A fill (hi/lo) via cp.async — overlaps the reduce/sx phases
    {
        const char* sh = (const char*)(g_norh + (size_t)iBase * NN + jBase);
        const char* sl = (const char*)(g_norl + (size_t)iBase * NN + jBase);
        #pragma unroll
        for (int i = 0; i < 2; i++) {
            int idx = t + i * 512;            // 0..1023 = 64 rows x 16 segs
            int row = idx >> 4, seg = idx & 15;
            CP16(dsm_b + OP_NORH + row * 272 + seg * 16,
                 sh + (size_t)row * 1024 + seg * 16);
            CP16(dsm_b + OP_NORL + row * 272 + seg * 16,
                 sl + (size_t)row * 1024 + seg * 16);
        }
        CP_COMMIT();
    }

    // Wlin/blin to smem
    if (t < 256) wlin[t] = Wlin[t];
    else if (t < 320) blin_s[t - 256] = blin[t - 256];

    // T reduce + c partials: h = t>>7 doubles as partial-group index
    {
        int h = t >> 7, jl = t & 127;
        float s = 0.f;
        #pragma unroll
        for (int ch = 0; ch < NCHT; ch++)
            s += g_Tpart[ch * (BB * HH * NN) + (b * HH + h) * NN + jBase + jl];
        Ts[h * 128 + jl] = s;
        float cse = 0.f;
        #pragma unroll
        for (int p = 0; p < 8; p++)
            cse += g_cpart[(h * 8 + p) * NN + jBase + jl];
        redC[h * 128 + jl] = cse;
    }
    __syncthreads();
    if (t < 128) cs[t] = redC[t] + redC[128 + t] + redC[256 + t] + redC[384 + t];
    __syncthreads();

    // sx hi/lo into smem: g = f-octet, 2 passes over j
    {
        const int g = t >> 6, j0 = t & 63;
        const int f0 = g * 8;
        #pragma unroll
        for (int p = 0; p < 2; p++) {
            int jl = p * 64 + j0;
            int jg = jBase + jl;
            const float* xp = x + ((size_t)(b * NN) + jg) * FF + f0;
            float4 xa = *(const float4*)xp;
            float4 xb = *(const float4*)(xp + 4);
            float xv[8] = {xa.x, xa.y, xa.z, xa.w, xb.x, xb.y, xb.z, xb.w};
            float cj = cs[jl];
            float th[HH];
            #pragma unroll
            for (int h = 0; h < HH; h++) th[h] = Ts[h * 128 + jl];
            #pragma unroll
            for (int i = 0; i < 8; i++) {
                float s = cj * blin_s[f0 + i];
                #pragma unroll
                for (int h = 0; h < HH; h++) s += th[h] * wlin[h * FF + f0 + i];
                float v = xv[i] * s;
                __nv_bfloat16 hb = __float2bfloat16(v);
                sxh[(f0 + i) * 136 + jl] = hb;
                sxl[(f0 + i) * 136 + jl] =
                    __float2bfloat16(v - __bfloat162float(hb));
            }
        }
    }
    CP_WAIT0();
    __syncthreads();

    // MMA: M64 x N64 x K128, hi*hi + hi*lo + lo*hi
    float acc0[4] = {0.f, 0.f, 0.f, 0.f};
    float acc1[4] = {0.f, 0.f, 0.f, 0.f};

    const int arow = ms * 16 + (lane & 7) + ((lane >> 3) & 1) * 8;
    const uint32_t aoff = (uint32_t)(arow * 272 + (lane >> 4) * 16);
    const uint32_t nh = dsm_b + OP_NORH, nl = dsm_b + OP_NORL;
    const uint32_t bb0 = (uint32_t)((ns * 16 + (lane & 7)) * 272 + (lane >> 3) * 16);
    const uint32_t bb1 = bb0 + 8 * 272;
    const uint32_t sh_b = dsm_b + OP_SXH, sl_b = dsm_b + OP_SXL;

    #pragma unroll
    for (int kg = 0; kg < 4; kg++) {
        uint32_t Ah0[4], Ah1[4], Al0[4], Al1[4];
        ldsm4(Ah0, nh + aoff + (kg * 2) * 32);
        ldsm4(Ah1, nh + aoff + (kg * 2 + 1) * 32);
        ldsm4(Al0, nl + aoff + (kg * 2) * 32);
        ldsm4(Al1, nl + aoff + (kg * 2 + 1) * 32);
        uint32_t Bh0[4], Bh1[4], Bl0[4], Bl1[4];
        ldsm4(Bh0, sh_b + bb0 + kg * 64);
        ldsm4(Bh1, sh_b + bb1 + kg * 64);
        ldsm4(Bl0, sl_b + bb0 + kg * 64);
        ldsm4(Bl1, sl_b + bb1 + kg * 64);

        mma16816(acc0, Ah0, Bh0);     mma16816(acc0, Ah1, Bh0 + 2);
        mma16816(acc1, Ah0, Bh1);     mma16816(acc1, Ah1, Bh1 + 2);
        mma16816(acc0, Ah0, Bl0);     mma16816(acc0, Ah1, Bl0 + 2);
        mma16816(acc1, Ah0, Bl1);     mma16816(acc1, Ah1, Bl1 + 2);
        mma16816(acc0, Al0, Bh0);     mma16816(acc0, Al1, Bh0 + 2);
        mma16816(acc1, Al0, Bh1);     mma16816(acc1, Al1, Bh1 + 2);
    }

    // write partial directly to g_opart
    {
        int r = lane >> 2, c2 = (lane & 3) * 2;
        float* op = g_opart +
            ((size_t)((ks * BB + b) * NN) + iBase + ms * 16 + r) * FF + ns * 16 + c2;
        float* op2 = op + 8 * FF;
        *(float2*)&op[0] = make_float2(acc0[0], acc0[1]);
        *(float2*)&op[8] = make_float2(acc1[0], acc1[1]);
        *(float2*)&op2[0] = make_float2(acc0[2], acc0[3]);
        *(float2*)&op2[8] = make_float2(acc1[2], acc1[3]);
    }
}

// ---------------- K4b: reduce 4 ksplits + fc + relu ----------------------
// grid (8 mtile, 4 b) = 32 blocks, 512 threads.
__global__ __launch_bounds__(512) void k_out_fc(const float* __restrict__ Wfc,
                                                const float* __restrict__ bfc,
                                                float* __restrict__ out) {
    __shared__ float wfcs[64 * 64];
    __shared__ float tmp[64][68];
    const int mtile = blockIdx.x, b = blockIdx.y;
    const int iBase = mtile * 64;
    const int t = threadIdx.x;

    #pragma unroll
    for (int i = 0; i < 2; i++)
        ((float4*)wfcs)[t + i * 512] = ((const float4*)Wfc)[t + i * 512];

    {
        int base = t * 8;                 // 0..4095
        int row = base >> 6, col = base & 63;
        float4 s0 = make_float4(0.f, 0.f, 0.f, 0.f);
        float4 s1 = make_float4(0.f, 0.f, 0.f, 0.f);
        #pragma unroll
        for (int ksp = 0; ksp < 4; ksp++) {
            const float* pp = g_opart +
                ((size_t)((ksp * BB + b) * NN) + iBase + row) * FF + col;
            float4 a = *(const float4*)pp;
            float4 c = *(const float4*)(pp + 4);
            s0.x += a.x; s0.y += a.y; s0.z += a.z; s0.w += a.w;
            s1.x += c.x; s1.y += c.y; s1.z += c.z; s1.w += c.w;
        }
        *(float4*)&tmp[row][col] = s0;
        *(float4*)&tmp[row][col + 4] = s1;
    }
    __syncthreads();

    {
        int row = t >> 3, fo = (t & 7) * 8;
        float o[8];
        #pragma unroll
        for (int i = 0; i < 8; i++) o[i] = bfc[fo + i];
        #pragma unroll 8
        for (int ff = 0; ff < 64; ff++) {
            float a = tmp[row][ff];
            const float* wr = wfcs + ff * 64 + fo;
            #pragma unroll
            for (int i = 0; i < 8; i++) o[i] += a * wr[i];
        }
        float* op = out + ((size_t)(b * NN) + iBase + row) * FF + fo;
        #pragma unroll
        for (int i = 0; i < 8; i++) op[i] = fmaxf(o[i], 0.f);
    }
}

// ---------------- launch ----------------
extern "C" void kernel_launch(void* const* d_in, const int* in_sizes, int n_in,
                              void* d_out, int out_size) {
    const float* x    = (const float*)d_in[0];
    const float* adj  = (const float*)d_in[1];
    const float* Wq   = (const float*)d_in[2];
    const float* bq   = (const float*)d_in[3];
    const float* Wk   = (const float*)d_in[4];
    const float* bk   = (const float*)d_in[5];
    const float* Wlin = (const float*)d_in[6];
    const float* blin = (const float*)d_in[7];
    const float* Wfc  = (const float*)d_in[8];
    const float* bfc  = (const float*)d_in[9];
    float* out = (float*)d_out;

    static int attr_set = 0;
    if (!attr_set) {
        cudaFuncSetAttribute(k_attn_mma,
                             cudaFuncAttributeMaxDynamicSharedMemorySize, ATTN_DSM);
        cudaFuncSetAttribute(k_out_part,
                             cudaFuncAttributeMaxDynamicSharedMemorySize, OP_DSM);
        attr_set = 1;
    }

    k_deg<<<NN, 256>>>(adj);
    k_nor_proj<<<288, 512>>>(adj, x, Wq, bq, Wk, bk);
    k_attn_mma<<<dim3(8, HH, BB), 512, ATTN_DSM>>>();
    k_out_part<<<dim3(8, BB, 4), 512, OP_DSM>>>(x, Wlin, blin);
    k_out_fc<<<dim3(8, BB), 512>>>(Wfc, bfc, out);
}

// round 17
// speedup vs baseline: 1.3506x; 1.1835x over previous
#include <cuda_runtime.h>
#include <cuda_bf16.h>
#include <math_constants.h>
#include <cstdint>

#define NN 512
#define BB 4
#define HH 4
#define FF 64
#define NCHT 8      // T-partial chunks = 8 m-tiles of 64 rows

// ---------------- scratch (device globals; no allocation) ----------------
__device__ float g_d[NN];
__device__ float g_cpart[32 * NN];
__device__ float g_nor[NN * NN];
__device__ __nv_bfloat16 g_norh[NN * NN];          // nor hi (bf16)
__device__ __nv_bfloat16 g_norl[NN * NN];          // nor lo
__device__ __nv_bfloat16 g_qh[BB * HH * NN * FF];  // q hi (pre-scaled 1/8)
__device__ __nv_bfloat16 g_ql[BB * HH * NN * FF];  // q lo
__device__ __nv_bfloat16 g_kh[BB * HH * NN * FF];  // k hi
__device__ __nv_bfloat16 g_kl[BB * HH * NN * FF];  // k lo
__device__ float g_Tpart[NCHT * BB * HH * NN];
__device__ float g_opart[4 * BB * NN * FF];        // [ks][b][512][64] fp32

// ---------------- HMMA m16n8k16 bf16 -> f32 ----------------
__device__ __forceinline__ void mma16816(float d[4], const uint32_t a[4],
                                         const uint32_t b[2]) {
    asm volatile(
        "mma.sync.aligned.m16n8k16.row.col.f32.bf16.bf16.f32 "
        "{%0,%1,%2,%3}, {%4,%5,%6,%7}, {%8,%9}, {%0,%1,%2,%3};"
        : "+f"(d[0]), "+f"(d[1]), "+f"(d[2]), "+f"(d[3])
        : "r"(a[0]), "r"(a[1]), "r"(a[2]), "r"(a[3]), "r"(b[0]), "r"(b[1]));
}

__device__ __forceinline__ uint32_t smem_u32(const void* p) {
    uint32_t r;
    asm("{ .reg .u64 t; cvta.to.shared.u64 t, %1; cvt.u32.u64 %0, t; }"
        : "=r"(r) : "l"(p));
    return r;
}
__device__ __forceinline__ void ldsm4(uint32_t r[4], uint32_t addr) {
    asm volatile("ldmatrix.sync.aligned.m8n8.x4.shared.b16 {%0,%1,%2,%3}, [%4];"
                 : "=r"(r[0]), "=r"(r[1]), "=r"(r[2]), "=r"(r[3]) : "r"(addr));
}

// ---------------- cp.async + mbarrier ----------------
#define CP16(dst, src) \
    asm volatile("cp.async.cg.shared.global [%0], [%1], 16;" \
                 :: "r"(dst), "l"(__cvta_generic_to_global(src)) : "memory")
#define CP_ARRIVE(mb) \
    asm volatile("cp.async.mbarrier.arrive.noinc.shared.b64 [%0];" :: "r"(mb) : "memory")
#define CP_COMMIT() asm volatile("cp.async.commit_group;" ::: "memory")
#define CP_WAIT0() asm volatile("cp.async.wait_group 0;" ::: "memory")
#define MBAR_INIT(mb, n) \
    asm volatile("mbarrier.init.shared.b64 [%0], %1;" :: "r"(mb), "r"((uint32_t)(n)) : "memory")
#define MBAR_WAIT(mb, ph) do { \
    asm volatile( \
        "{\n\t.reg .pred P1;\n\t" \
        "WAIT_LOOP_%=:\n\t" \
        "mbarrier.try_wait.parity.acquire.cta.shared::cta.b64 P1, [%0], %1, 0x989680;\n\t" \
        "@P1 bra.uni WAIT_DONE_%=;\n\t" \
        "bra.uni WAIT_LOOP_%=;\n\t" \
        "WAIT_DONE_%=:\n\t}" \
        :: "r"(mb), "r"((uint32_t)(ph)) : "memory"); \
} while (0)

__device__ __forceinline__ float blockReduceSum256(float v, float* red) {
    #pragma unroll
    for (int o = 16; o; o >>= 1) v += __shfl_xor_sync(0xffffffffu, v, o);
    int wid = threadIdx.x >> 5, lane = threadIdx.x & 31;
    if (lane == 0) red[wid] = v;
    __syncthreads();
    float r = (threadIdx.x < 8) ? red[threadIdx.x] : 0.f;
    if (wid == 0) {
        #pragma unroll
        for (int o = 4; o; o >>= 1) r += __shfl_xor_sync(0xffffffffu, r, o);
    }
    return r;
}

// ---------------- K1a: degrees ----------------
__global__ void k_deg(const float* __restrict__ adj) {
    __shared__ float red[8];
    int i = blockIdx.x;
    float s = 0.f;
    for (int j = threadIdx.x; j < NN; j += 256) s += adj[i * NN + j];
    s = blockReduceSum256(s, red);
    if (threadIdx.x == 0) g_d[i] = rsqrtf(s + 1.0f);
}

// ---------------- K1b: normalized adjacency (32 blocks x 512) -----------
__global__ __launch_bounds__(512) void k_nor(const float* __restrict__ adj) {
    const int bk_ = blockIdx.x;
    const int j = threadIdx.x;
    const float dj = g_d[j];
    float s = 0.f;
    #pragma unroll
    for (int r = 0; r < 16; r++) {
        int i = bk_ * 16 + r;
        float a = adj[i * NN + j] + (i == j ? 1.0f : 0.0f);
        float v = g_d[i] * dj * a;
        g_nor[i * NN + j] = v;
        __nv_bfloat16 hb = __float2bfloat16(v);
        g_norh[i * NN + j] = hb;
        g_norl[i * NN + j] = __float2bfloat16(v - __bfloat162float(hb));
        s += v;
    }
    g_cpart[bk_ * NN + j] = s;
}

// ---------------- K2: q/k projections -> bf16 hi/lo (independent of deg) -
__global__ __launch_bounds__(256) void k_proj(const float* __restrict__ x,
                                              const float* __restrict__ Wq,
                                              const float* __restrict__ bq,
                                              const float* __restrict__ Wk,
                                              const float* __restrict__ bk) {
    const int by = blockIdx.y;
    const bool isK = by >= 4;
    const float* W = isK ? Wk : Wq;
    const float* bias = isK ? bk : bq;
    const int h = isK ? by - 4 : by;
    const int c0 = h * 64;
    const int rowBase = blockIdx.x * 64;
    const int b = rowBase >> 9;
    const int bh = b * HH + h;
    const int nb = rowBase & 511;

    __shared__ float xs[64][65];
    __shared__ float ws[64][64];

    const int t = threadIdx.x;
    #pragma unroll
    for (int i = 0; i < 4; i++) {
        int lin4 = t + i * 256;
        int r = lin4 >> 4, c4 = (lin4 & 15) * 4;
        float4 v = *(const float4*)(x + rowBase * 64 + lin4 * 4);
        xs[r][c4] = v.x; xs[r][c4 + 1] = v.y; xs[r][c4 + 2] = v.z; xs[r][c4 + 3] = v.w;
        *(float4*)&ws[r][c4] = *(const float4*)(W + r * 256 + c0 + c4);
    }
    __syncthreads();

    const int tx = t & 15, ty = t >> 4;
    float acc[4][4];
    #pragma unroll
    for (int i = 0; i < 4; i++)
        #pragma unroll
        for (int jj = 0; jj < 4; jj++) acc[i][jj] = 0.f;

    #pragma unroll 8
    for (int k = 0; k < 64; k++) {
        float a0 = xs[4 * ty + 0][k];
        float a1 = xs[4 * ty + 1][k];
        float a2 = xs[4 * ty + 2][k];
        float a3 = xs[4 * ty + 3][k];
        float4 bv = *(float4*)&ws[k][4 * tx];
        acc[0][0] += a0 * bv.x; acc[0][1] += a0 * bv.y; acc[0][2] += a0 * bv.z; acc[0][3] += a0 * bv.w;
        acc[1][0] += a1 * bv.x; acc[1][1] += a1 * bv.y; acc[1][2] += a1 * bv.z; acc[1][3] += a1 * bv.w;
        acc[2][0] += a2 * bv.x; acc[2][1] += a2 * bv.y; acc[2][2] += a2 * bv.z; acc[2][3] += a2 * bv.w;
        acc[3][0] += a3 * bv.x; acc[3][1] += a3 * bv.y; acc[3][2] += a3 * bv.z; acc[3][3] += a3 * bv.w;
    }

    float4 bb = *(const float4*)&bias[c0 + 4 * tx];
    const float sc = isK ? 1.0f : 0.125f;
    __nv_bfloat16* dh = isK ? g_kh : g_qh;
    __nv_bfloat16* dl = isK ? g_kl : g_ql;
    #pragma unroll
    for (int rr = 0; rr < 4; rr++) {
        int n = nb + 4 * ty + rr;
        size_t o = (size_t)(bh * NN + n) * FF + 4 * tx;
        float v0 = (acc[rr][0] + bb.x) * sc;
        float v1 = (acc[rr][1] + bb.y) * sc;
        float v2 = (acc[rr][2] + bb.z) * sc;
        float v3 = (acc[rr][3] + bb.w) * sc;
        __nv_bfloat16 h0 = __float2bfloat16(v0), h1 = __float2bfloat16(v1);
        __nv_bfloat16 h2 = __float2bfloat16(v2), h3 = __float2bfloat16(v3);
        *(__nv_bfloat162*)&dh[o]     = __halves2bfloat162(h0, h1);
        *(__nv_bfloat162*)&dh[o + 2] = __halves2bfloat162(h2, h3);
        *(__nv_bfloat162*)&dl[o] = __halves2bfloat162(
            __float2bfloat16(v0 - __bfloat162float(h0)),
            __float2bfloat16(v1 - __bfloat162float(h1)));
        *(__nv_bfloat162*)&dl[o + 2] = __halves2bfloat162(
            __float2bfloat16(v2 - __bfloat162float(h2)),
            __float2bfloat16(v3 - __bfloat162float(h3)));
    }
}

// ---------------- K3: HMMA scores, cp.async-pipelined (unchanged) -------
#define ATTN_DSM 223232
__global__ __launch_bounds__(512, 1) void k_attn_mma() {
    extern __shared__ __align__(16) char dsm[];
    __nv_bfloat16* qh_s = (__nv_bfloat16*)dsm;
    __nv_bfloat16* kh_s = (__nv_bfloat16*)(dsm + 9216);
    __nv_bfloat16* kl_s = (__nv_bfloat16*)(dsm + 82944);
    __nv_bfloat16* expb = (__nv_bfloat16*)(dsm + 156672);

    __shared__ unsigned long long mbars[4];
    __shared__ float rsum[4][64];
    __shared__ float rinv[64];

    const int mtile = blockIdx.x, h = blockIdx.y, b = blockIdx.z;
    const int bh = b * HH + h;
    const int iBase = mtile * 64;
    const int tid = threadIdx.x;
    const int w = tid >> 5, lane = tid & 31;
    const int mrow = (w >> 2) * 16;
    const int cs = w & 3;
    const int r = lane >> 2, c = lane & 3;

    const uint32_t qh_b = smem_u32(qh_s);
    const uint32_t kh_b = smem_u32(kh_s);
    const uint32_t kl_b = smem_u32(kl_s);

    if (tid < 4) MBAR_INIT(smem_u32(&mbars[tid]), 512);

    {
        const uint4* sh = (const uint4*)(g_qh + (size_t)(bh * NN + iBase) * FF);
        int row = tid >> 3, c8 = tid & 7;
        *(uint4*)&qh_s[row * 72 + c8 * 8] = sh[tid];
    }
    __syncthreads();

    {
        const char* khg = (const char*)(g_kh + (size_t)bh * NN * FF);
        const char* klg = (const char*)(g_kl + (size_t)bh * NN * FF);
        #pragma unroll
        for (int ch = 0; ch < 4; ch++) {
            #pragma unroll
            for (int i = 0; i < 2; i++) {
                int idx = tid + i * 512;
                int row = ch * 128 + (idx >> 3), c8 = idx & 7;
                CP16(kh_b + (uint32_t)(row * 144 + c8 * 16), khg + row * 128 + c8 * 16);
                CP16(kl_b + (uint32_t)(row * 144 + c8 * 16), klg + row * 128 + c8 * 16);
            }
            CP_ARRIVE(smem_u32(&mbars[ch]));
        }
    }

    uint32_t qhA[4][4], qlA[4][4];
    {
        const int arow = mrow + (lane & 7) + ((lane >> 3) & 1) * 8;
        const uint32_t aoff = (uint32_t)(arow * 72 + (lane >> 4) * 8) * 2;
        #pragma unroll
        for (int kt = 0; kt < 4; kt++) ldsm4(qhA[kt], qh_b + aoff + kt * 32);
        const __nv_bfloat16* qlg = g_ql + (size_t)(bh * NN + iBase) * FF;
        #pragma unroll
        for (int kt = 0; kt < 4; kt++) {
            int col = kt * 16 + 2 * c;
            qlA[kt][0] = *(const uint32_t*)&qlg[(mrow + r) * 64 + col];
            qlA[kt][1] = *(const uint32_t*)&qlg[(mrow + r + 8) * 64 + col];
            qlA[kt][2] = *(const uint32_t*)&qlg[(mrow + r) * 64 + col + 8];
            qlA[kt][3] = *(const uint32_t*)&qlg[(mrow + r + 8) * 64 + col + 8];
        }
    }

    MBAR_WAIT(smem_u32(&mbars[cs]), 0);

    float rs0 = 0.f, rs1 = 0.f;
    const int brow0 = cs * 128 + (lane & 7);
    const uint32_t boff_lane = (uint32_t)((lane >> 3) * 16);

    #pragma unroll 2
    for (int nt = 0; nt < 16; nt++) {
        const uint32_t bb = (uint32_t)((brow0 + nt * 8) * 144) + boff_lane;
        uint32_t khx[8], klx[8];
        ldsm4(khx, kh_b + bb);
        ldsm4(khx + 4, kh_b + bb + 64);
        ldsm4(klx, kl_b + bb);
        ldsm4(klx + 4, kl_b + bb + 64);

        float d0[4] = {0.f, 0.f, 0.f, 0.f};
        float d1[4] = {0.f, 0.f, 0.f, 0.f};
        float d2[4] = {0.f, 0.f, 0.f, 0.f};
        #pragma unroll
        for (int kt = 0; kt < 4; kt++) {
            mma16816(d0, qhA[kt], khx + 2 * kt);
            mma16816(d1, qhA[kt], klx + 2 * kt);
            mma16816(d2, qlA[kt], khx + 2 * kt);
        }
        float e0 = __expf(d0[0] + d1[0] + d2[0]);
        float e1 = __expf(d0[1] + d1[1] + d2[1]);
        float e2 = __expf(d0[2] + d1[2] + d2[2]);
        float e3 = __expf(d0[3] + d1[3] + d2[3]);
        rs0 += e0 + e1;
        rs1 += e2 + e3;
        int gcol = cs * 128 + nt * 8 + 2 * c;
        *(__nv_bfloat162*)&expb[(mrow + r) * 520 + gcol] =
            __halves2bfloat162(__float2bfloat16(e0), __float2bfloat16(e1));
        *(__nv_bfloat162*)&expb[(mrow + r + 8) * 520 + gcol] =
            __halves2bfloat162(__float2bfloat16(e2), __float2bfloat16(e3));
    }

    rs0 += __shfl_xor_sync(0xffffffffu, rs0, 1);
    rs0 += __shfl_xor_sync(0xffffffffu, rs0, 2);
    rs1 += __shfl_xor_sync(0xffffffffu, rs1, 1);
    rs1 += __shfl_xor_sync(0xffffffffu, rs1, 2);
    if ((lane & 3) == 0) {
        rsum[cs][mrow + r] = rs0;
        rsum[cs][mrow + r + 8] = rs1;
    }
    __syncthreads();
    if (tid < 64)
        rinv[tid] = 1.0f / (rsum[0][tid] + rsum[1][tid] + rsum[2][tid] + rsum[3][tid]);
    __syncthreads();

    {
        const float* np = g_nor + (size_t)iBase * NN;
        float a0 = 0.f, a1 = 0.f;
        #pragma unroll 8
        for (int i = 0; i < 64; i += 2) {
            a0 += np[i * NN + tid] *
                  (__bfloat162float(expb[i * 520 + tid]) * rinv[i]);
            a1 += np[(i + 1) * NN + tid] *
                  (__bfloat162float(expb[(i + 1) * 520 + tid]) * rinv[i + 1]);
        }
        g_Tpart[mtile * (BB * HH * NN) + bh * NN + tid] = a0 + a1;
    }
}

// ---------------- K4a: k-split partial out (unchanged from R16) ----------
#define OP_SXH  0
#define OP_SXL  17408
#define OP_NORH 34816
#define OP_NORL 52224
#define OP_TS   69632
#define OP_CS   71680
#define OP_REDC 72192
#define OP_WLIN 74240
#define OP_BLIN 75264
#define OP_DSM  75520
__global__ __launch_bounds__(512, 1) void k_out_part(const float* __restrict__ x,
                                                     const float* __restrict__ Wlin,
                                                     const float* __restrict__ blin) {
    extern __shared__ __align__(16) char dsm[];
    __nv_bfloat16* sxh = (__nv_bfloat16*)(dsm + OP_SXH);   // [64 f][136 j]
    __nv_bfloat16* sxl = (__nv_bfloat16*)(dsm + OP_SXL);
    float* Ts = (float*)(dsm + OP_TS);
    float* cs = (float*)(dsm + OP_CS);
    float* redC = (float*)(dsm + OP_REDC);
    float* wlin = (float*)(dsm + OP_WLIN);
    float* blin_s = (float*)(dsm + OP_BLIN);

    const int mtile = blockIdx.x, b = blockIdx.y, ks = blockIdx.z;
    const int iBase = mtile * 64;
    const int jBase = ks * 128;
    const int t = threadIdx.x, w = t >> 5, lane = t & 31;
    const int ms = w >> 2, ns = w & 3;
    const uint32_t dsm_b = smem_u32(dsm);

    {
        const char* sh = (const char*)(g_norh + (size_t)iBase * NN + jBase);
        const char* sl = (const char*)(g_norl + (size_t)iBase * NN + jBase);
        #pragma unroll
        for (int i = 0; i < 2; i++) {
            int idx = t + i * 512;
            int row = idx >> 4, seg = idx & 15;
            CP16(dsm_b + OP_NORH + row * 272 + seg * 16,
                 sh + (size_t)row * 1024 + seg * 16);
            CP16(dsm_b + OP_NORL + row * 272 + seg * 16,
                 sl + (size_t)row * 1024 + seg * 16);
        }
        CP_COMMIT();
    }

    if (t < 256) wlin[t] = Wlin[t];
    else if (t < 320) blin_s[t - 256] = blin[t - 256];

    {
        int h = t >> 7, jl = t & 127;
        float s = 0.f;
        #pragma unroll
        for (int ch = 0; ch < NCHT; ch++)
            s += g_Tpart[ch * (BB * HH * NN) + (b * HH + h) * NN + jBase + jl];
        Ts[h * 128 + jl] = s;
        float cse = 0.f;
        #pragma unroll
        for (int p = 0; p < 8; p++)
            cse += g_cpart[(h * 8 + p) * NN + jBase + jl];
        redC[h * 128 + jl] = cse;
    }
    __syncthreads();
    if (t < 128) cs[t] = redC[t] + redC[128 + t] + redC[256 + t] + redC[384 + t];
    __syncthreads();

    {
        const int g = t >> 6, j0 = t & 63;
        const int f0 = g * 8;
        #pragma unroll
        for (int p = 0; p < 2; p++) {
            int jl = p * 64 + j0;
            int jg = jBase + jl;
            const float* xp = x + ((size_t)(b * NN) + jg) * FF + f0;
            float4 xa = *(const float4*)xp;
            float4 xb = *(const float4*)(xp + 4);
            float xv[8] = {xa.x, xa.y, xa.z, xa.w, xb.x, xb.y, xb.z, xb.w};
            float cj = cs[jl];
            float th[HH];
            #pragma unroll
            for (int h = 0; h < HH; h++) th[h] = Ts[h * 128 + jl];
            #pragma unroll
            for (int i = 0; i < 8; i++) {
                float s = cj * blin_s[f0 + i];
                #pragma unroll
                for (int h = 0; h < HH; h++) s += th[h] * wlin[h * FF + f0 + i];
                float v = xv[i] * s;
                __nv_bfloat16 hb = __float2bfloat16(v);
                sxh[(f0 + i) * 136 + jl] = hb;
                sxl[(f0 + i) * 136 + jl] =
                    __float2bfloat16(v - __bfloat162float(hb));
            }
        }
    }
    CP_WAIT0();
    __syncthreads();

    float acc0[4] = {0.f, 0.f, 0.f, 0.f};
    float acc1[4] = {0.f, 0.f, 0.f, 0.f};

    const int arow = ms * 16 + (lane & 7) + ((lane >> 3) & 1) * 8;
    const uint32_t aoff = (uint32_t)(arow * 272 + (lane >> 4) * 16);
    const uint32_t nh = dsm_b + OP_NORH, nl = dsm_b + OP_NORL;
    const uint32_t bb0 = (uint32_t)((ns * 16 + (lane & 7)) * 272 + (lane >> 3) * 16);
    const uint32_t bb1 = bb0 + 8 * 272;
    const uint32_t sh_b = dsm_b + OP_SXH, sl_b = dsm_b + OP_SXL;

    #pragma unroll
    for (int kg = 0; kg < 4; kg++) {
        uint32_t Ah0[4], Ah1[4], Al0[4], Al1[4];
        ldsm4(Ah0, nh + aoff + (kg * 2) * 32);
        ldsm4(Ah1, nh + aoff + (kg * 2 + 1) * 32);
        ldsm4(Al0, nl + aoff + (kg * 2) * 32);
        ldsm4(Al1, nl + aoff + (kg * 2 + 1) * 32);
        uint32_t Bh0[4], Bh1[4], Bl0[4], Bl1[4];
        ldsm4(Bh0, sh_b + bb0 + kg * 64);
        ldsm4(Bh1, sh_b + bb1 + kg * 64);
        ldsm4(Bl0, sl_b + bb0 + kg * 64);
        ldsm4(Bl1, sl_b + bb1 + kg * 64);

        mma16816(acc0, Ah0, Bh0);     mma16816(acc0, Ah1, Bh0 + 2);
        mma16816(acc1, Ah0, Bh1);     mma16816(acc1, Ah1, Bh1 + 2);
        mma16816(acc0, Ah0, Bl0);     mma16816(acc0, Ah1, Bl0 + 2);
        mma16816(acc1, Ah0, Bl1);     mma16816(acc1, Ah1, Bl1 + 2);
        mma16816(acc0, Al0, Bh0);     mma16816(acc0, Al1, Bh0 + 2);
        mma16816(acc1, Al0, Bh1);     mma16816(acc1, Al1, Bh1 + 2);
    }

    {
        int r = lane >> 2, c2 = (lane & 3) * 2;
        float* op = g_opart +
            ((size_t)((ks * BB + b) * NN) + iBase + ms * 16 + r) * FF + ns * 16 + c2;
        float* op2 = op + 8 * FF;
        *(float2*)&op[0] = make_float2(acc0[0], acc0[1]);
        *(float2*)&op[8] = make_float2(acc1[0], acc1[1]);
        *(float2*)&op2[0] = make_float2(acc0[2], acc0[3]);
        *(float2*)&op2[8] = make_float2(acc1[2], acc1[3]);
    }
}

// ---------------- K4b: reduce 4 ksplits + fc + relu (128 blocks) ---------
// grid (32 row-tiles of 16, 4 b), 512 threads.
__global__ __launch_bounds__(512) void k_out_fc(const float* __restrict__ Wfc,
                                                const float* __restrict__ bfc,
                                                float* __restrict__ out) {
    __shared__ float wfcs[64 * 64];
    __shared__ float tmp[16][68];
    const int rtile = blockIdx.x, b = blockIdx.y;
    const int iBase = rtile * 16;
    const int t = threadIdx.x;

    #pragma unroll
    for (int i = 0; i < 2; i++)
        ((float4*)wfcs)[t + i * 512] = ((const float4*)Wfc)[t + i * 512];

    {
        int base = t * 2;                 // 0..1023 over 16x64
        int row = base >> 6, col = base & 63;
        float2 s0 = make_float2(0.f, 0.f);
        #pragma unroll
        for (int ksp = 0; ksp < 4; ksp++) {
            const float* pp = g_opart +
                ((size_t)((ksp * BB + b) * NN) + iBase + row) * FF + col;
            float2 a = *(const float2*)pp;
            s0.x += a.x; s0.y += a.y;
        }
        *(float2*)&tmp[row][col] = s0;
    }
    __syncthreads();

    {
        int row = t >> 5, fo = (t & 31) * 2;
        float o0 = bfc[fo], o1 = bfc[fo + 1];
        #pragma unroll 8
        for (int ff = 0; ff < 64; ff++) {
            float a = tmp[row][ff];
            const float* wr = wfcs + ff * 64 + fo;
            o0 += a * wr[0];
            o1 += a * wr[1];
        }
        float* op = out + ((size_t)(b * NN) + iBase + row) * FF + fo;
        *(float2*)op = make_float2(fmaxf(o0, 0.f), fmaxf(o1, 0.f));
    }
}

// ---------------- launch: forked-stream graph ---------------------------
extern "C" void kernel_launch(void* const* d_in, const int* in_sizes, int n_in,
                              void* d_out, int out_size) {
    const float* x    = (const float*)d_in[0];
    const float* adj  = (const float*)d_in[1];
    const float* Wq   = (const float*)d_in[2];
    const float* bq   = (const float*)d_in[3];
    const float* Wk   = (const float*)d_in[4];
    const float* bk   = (const float*)d_in[5];
    const float* Wlin = (const float*)d_in[6];
    const float* blin = (const float*)d_in[7];
    const float* Wfc  = (const float*)d_in[8];
    const float* bfc  = (const float*)d_in[9];
    float* out = (float*)d_out;

    static int init_done = 0;
    static cudaStream_t s1;
    static cudaEvent_t ev_fork, ev_join;
    if (!init_done) {
        cudaFuncSetAttribute(k_attn_mma,
                             cudaFuncAttributeMaxDynamicSharedMemorySize, ATTN_DSM);
        cudaFuncSetAttribute(k_out_part,
                             cudaFuncAttributeMaxDynamicSharedMemorySize, OP_DSM);
        cudaStreamCreateWithFlags(&s1, cudaStreamNonBlocking);
        cudaEventCreateWithFlags(&ev_fork, cudaEventDisableTiming);
        cudaEventCreateWithFlags(&ev_join, cudaEventDisableTiming);
        init_done = 1;
    }

    // fork: proj on s1, deg->nor on default stream, then join before attn.
    cudaEventRecord(ev_fork, 0);
    cudaStreamWaitEvent(s1, ev_fork, 0);
    k_proj<<<dim3(32, 8), 256, 0, s1>>>(x, Wq, bq, Wk, bk);
    cudaEventRecord(ev_join, s1);

    k_deg<<<NN, 256>>>(adj);
    k_nor<<<32, 512>>>(adj);

    cudaStreamWaitEvent(0, ev_join, 0);
    k_attn_mma<<<dim3(8, HH, BB), 512, ATTN_DSM>>>();
    k_out_part<<<dim3(8, BB, 4), 512, OP_DSM>>>(x, Wlin, blin);
    k_out_fc<<<dim3(32, BB), 512>>>(Wfc, bfc, out);
}